// round 11
// baseline (speedup 1.0000x reference)
#include <cuda_runtime.h>

// x: (4096, 32, 500) f32, W: (1,32) f32, b: (1,) f32 -> out: (4096,) f32
// out[s] = mean_a | sum_c W[c]*x[s][c][a] + b | + 0.01
//
// Split each sample across 2 CTAs (asset-dimension split; |.| is per-asset so
// partial sums combine additively). Last-arriving CTA combines in fixed index
// order (deterministic) and resets the counter for graph replays.

#define N_SAMPLES 4096
#define N_CH      32
#define N_ASSETS  500
#define VEC4_PER_ROW 125          // 500 / 4
#define THREADS   64
#define PARTS     2

__device__ float    g_part[N_SAMPLES * PARTS];
__device__ unsigned g_cnt[N_SAMPLES];           // zero-init at load; self-resetting

__global__ __launch_bounds__(THREADS)
void gamma_kernel(const float* __restrict__ x,
                  const float* __restrict__ W,
                  const float* __restrict__ b,
                  float* __restrict__ out)
{
    const int blk = blockIdx.x;
    const int s   = blk >> 1;          // sample
    const int p   = blk & 1;           // part: cols [0,64) or [64,125)
    const int tid = threadIdx.x;
    const int col = p * 64 + tid;

    __shared__ float ws[N_CH];
    __shared__ float bs;
    if (tid < N_CH) ws[tid] = W[tid];
    if (tid == N_CH) bs = b[0];
    __syncthreads();

    float4 acc = make_float4(0.f, 0.f, 0.f, 0.f);

    if (col < VEC4_PER_ROW) {
        const float4* base = reinterpret_cast<const float4*>(
                                 x + (size_t)s * (N_CH * N_ASSETS)) + col;
        #pragma unroll
        for (int c = 0; c < N_CH; ++c) {
            const float wc = ws[c];
            float4 v = base[c * VEC4_PER_ROW];
            acc.x = fmaf(wc, v.x, acc.x);
            acc.y = fmaf(wc, v.y, acc.y);
            acc.z = fmaf(wc, v.z, acc.z);
            acc.w = fmaf(wc, v.w, acc.w);
        }
    }

    const float bv = bs;
    float part = 0.f;
    if (col < VEC4_PER_ROW) {
        part = fabsf(acc.x + bv) + fabsf(acc.y + bv)
             + fabsf(acc.z + bv) + fabsf(acc.w + bv);
    }

    // warp reduce (2 warps)
    #pragma unroll
    for (int off = 16; off > 0; off >>= 1)
        part += __shfl_xor_sync(0xFFFFFFFFu, part, off);

    __shared__ float warp_sums[THREADS / 32];
    const int wid = tid >> 5;
    const int lid = tid & 31;
    if (lid == 0) warp_sums[wid] = part;
    __syncthreads();

    if (tid == 0) {
        float mypart = warp_sums[0] + warp_sums[1];
        g_part[2 * s + p] = mypart;
        __threadfence();
        unsigned old = atomicAdd(&g_cnt[s], 1u);
        if (old == 1u) {
            // last arriver: combine in fixed order -> deterministic
            __threadfence();
            float total = g_part[2 * s + 0] + g_part[2 * s + 1];
            out[s] = total * (1.0f / (float)N_ASSETS) + 0.01f;
            atomicExch(&g_cnt[s], 0u);   // reset for next graph replay
        }
    }
}

extern "C" void kernel_launch(void* const* d_in, const int* in_sizes, int n_in,
                              void* d_out, int out_size)
{
    const float* x = (const float*)d_in[0];
    const float* W = (const float*)d_in[1];
    const float* b = (const float*)d_in[2];
    float* out = (float*)d_out;
    (void)in_sizes; (void)n_in; (void)out_size;

    gamma_kernel<<<N_SAMPLES * PARTS, THREADS>>>(x, W, b, out);
}

// round 12
// speedup vs baseline: 1.1269x; 1.1269x over previous
#include <cuda_runtime.h>

// x: (4096, 32, 500) f32, W: (1,32) f32, b: (1,) f32 -> out: (4096,) f32
// out[s] = mean_a | sum_c W[c]*x[s][c][a] + b | + 0.01
//
// R5 skeleton (best: 41.44us) + streaming (evict-first) loads for the
// read-once 262MB x tensor.

#define N_SAMPLES 4096
#define N_CH      32
#define N_ASSETS  500
#define VEC4_PER_ROW 125          // 500 / 4
#define THREADS   128

__global__ __launch_bounds__(THREADS)
void gamma_kernel(const float* __restrict__ x,
                  const float* __restrict__ W,
                  const float* __restrict__ b,
                  float* __restrict__ out)
{
    const int s   = blockIdx.x;
    const int tid = threadIdx.x;

    __shared__ float ws[N_CH];
    __shared__ float bs;
    if (tid < N_CH) ws[tid] = W[tid];
    if (tid == N_CH) bs = b[0];
    __syncthreads();

    const float* xs = x + (size_t)s * (N_CH * N_ASSETS);

    float4 acc = make_float4(0.f, 0.f, 0.f, 0.f);

    if (tid < VEC4_PER_ROW) {
        const float4* base = reinterpret_cast<const float4*>(xs) + tid;
        #pragma unroll
        for (int c = 0; c < N_CH; ++c) {
            const float wc = ws[c];
            float4 v = __ldcs(&base[c * VEC4_PER_ROW]);   // evict-first stream
            acc.x = fmaf(wc, v.x, acc.x);
            acc.y = fmaf(wc, v.y, acc.y);
            acc.z = fmaf(wc, v.z, acc.z);
            acc.w = fmaf(wc, v.w, acc.w);
        }
    }

    const float bv = bs;
    float part = 0.f;
    if (tid < VEC4_PER_ROW) {
        part = fabsf(acc.x + bv) + fabsf(acc.y + bv)
             + fabsf(acc.z + bv) + fabsf(acc.w + bv);
    }

    // warp reduce
    #pragma unroll
    for (int off = 16; off > 0; off >>= 1)
        part += __shfl_xor_sync(0xFFFFFFFFu, part, off);

    __shared__ float warp_sums[THREADS / 32];
    const int wid = tid >> 5;
    const int lid = tid & 31;
    if (lid == 0) warp_sums[wid] = part;
    __syncthreads();

    if (tid == 0) {
        float total = warp_sums[0] + warp_sums[1] + warp_sums[2] + warp_sums[3];
        out[s] = total * (1.0f / (float)N_ASSETS) + 0.01f;
    }
}

extern "C" void kernel_launch(void* const* d_in, const int* in_sizes, int n_in,
                              void* d_out, int out_size)
{
    const float* x = (const float*)d_in[0];
    const float* W = (const float*)d_in[1];
    const float* b = (const float*)d_in[2];
    float* out = (float*)d_out;
    (void)in_sizes; (void)n_in; (void)out_size;

    gamma_kernel<<<N_SAMPLES, THREADS>>>(x, W, b, out);
}

// round 13
// speedup vs baseline: 1.1582x; 1.0278x over previous
#include <cuda_runtime.h>

// x: (4096, 32, 500) f32, W: (1,32) f32, b: (1,) f32 -> out: (4096,) f32
// out[s] = mean_a | sum_c W[c]*x[s][c][a] + b | + 0.01
//
// R5 skeleton + 8-deep explicit load batching, with __launch_bounds__(128,12)
// so ptxas is PERMITTED ~42 regs and actually keeps the 8 float4 loads in
// flight (R2's attempt was silently serialized back to 32 regs).

#define N_SAMPLES 4096
#define N_CH      32
#define N_ASSETS  500
#define VEC4_PER_ROW 125          // 500 / 4
#define THREADS   128
#define CBATCH    8

__global__ __launch_bounds__(THREADS, 12)
void gamma_kernel(const float* __restrict__ x,
                  const float* __restrict__ W,
                  const float* __restrict__ b,
                  float* __restrict__ out)
{
    const int s   = blockIdx.x;
    const int tid = threadIdx.x;

    __shared__ float ws[N_CH];
    __shared__ float bs;
    if (tid < N_CH) ws[tid] = W[tid];
    if (tid == N_CH) bs = b[0];
    __syncthreads();

    const float* xs = x + (size_t)s * (N_CH * N_ASSETS);

    float4 acc = make_float4(0.f, 0.f, 0.f, 0.f);

    if (tid < VEC4_PER_ROW) {
        const float4* base = reinterpret_cast<const float4*>(xs) + tid;
        #pragma unroll
        for (int cb = 0; cb < N_CH; cb += CBATCH) {
            float4 v[CBATCH];
            // front-batch 8 independent LDG.128s (needs the reg headroom
            // granted by launch_bounds(128, 12))
            #pragma unroll
            for (int i = 0; i < CBATCH; ++i)
                v[i] = base[(cb + i) * VEC4_PER_ROW];
            #pragma unroll
            for (int i = 0; i < CBATCH; ++i) {
                const float wc = ws[cb + i];
                acc.x = fmaf(wc, v[i].x, acc.x);
                acc.y = fmaf(wc, v[i].y, acc.y);
                acc.z = fmaf(wc, v[i].z, acc.z);
                acc.w = fmaf(wc, v[i].w, acc.w);
            }
        }
    }

    const float bv = bs;
    float part = 0.f;
    if (tid < VEC4_PER_ROW) {
        part = fabsf(acc.x + bv) + fabsf(acc.y + bv)
             + fabsf(acc.z + bv) + fabsf(acc.w + bv);
    }

    // warp reduce
    #pragma unroll
    for (int off = 16; off > 0; off >>= 1)
        part += __shfl_xor_sync(0xFFFFFFFFu, part, off);

    __shared__ float warp_sums[THREADS / 32];
    const int wid = tid >> 5;
    const int lid = tid & 31;
    if (lid == 0) warp_sums[wid] = part;
    __syncthreads();

    if (tid == 0) {
        float total = warp_sums[0] + warp_sums[1] + warp_sums[2] + warp_sums[3];
        out[s] = total * (1.0f / (float)N_ASSETS) + 0.01f;
    }
}

extern "C" void kernel_launch(void* const* d_in, const int* in_sizes, int n_in,
                              void* d_out, int out_size)
{
    const float* x = (const float*)d_in[0];
    const float* W = (const float*)d_in[1];
    const float* b = (const float*)d_in[2];
    float* out = (float*)d_out;
    (void)in_sizes; (void)n_in; (void)out_size;

    gamma_kernel<<<N_SAMPLES, THREADS>>>(x, W, b, out);
}